// round 12
// baseline (speedup 1.0000x reference)
#include <cuda_runtime.h>

namespace {
constexpr int PNP = 4;
constexpr int MOD = 4;
constexpr int NCH = 100;
constexpr int F   = NCH + PNP;       // 104
constexpr int XW  = PNP * (1 + MOD); // 20
constexpr int NT  = 224;             // 56 groups x 4 lanes; group = 2 rows
constexpr int QSZ = 4 * 7 * 4 * 4;   // modes x units x quarters x 4 floats = 448
constexpr float C0F   = 299792458.0f;
constexpr float ALPHA = 2.3025850929940457e-4f;
}

using ull = unsigned long long;

__device__ __forceinline__ ull pk2(float a, float b) {
    ull r; asm("mov.b64 %0,{%1,%2};" : "=l"(r) : "f"(a), "f"(b)); return r;
}
__device__ __forceinline__ void fma2(ull& d, ull a, ull b) {
    asm("fma.rn.f32x2 %0,%1,%2,%0;" : "+l"(d) : "l"(a), "l"(b));
}
__device__ __forceinline__ float up2sum(ull v) {
    float lo, hi; asm("mov.b64 {%0,%1},%2;" : "=f"(lo), "=f"(hi) : "l"(v));
    return lo + hi;
}

__device__ __forceinline__ float gain_of(float fi, float fj,
                                         const float* __restrict__ raman,
                                         float scale, int Lr) {
    const float fd = fj - fi;
    const float pos = fabsf(fd) * scale;
    int i0 = (int)floorf(pos);
    i0 = min(max(i0, 0), Lr - 2);
    const float w = pos - (float)i0;
    float g = raman[i0] * (1.0f - w) + raman[i0 + 1] * w;
    if (fd < 0.0f) g = -g;
    return g * fmaxf(1.0f, fi / fj);
}

__global__ __launch_bounds__(NT, 4) void raman_kernel(
    const float* __restrict__ x,
    const float* __restrict__ sig_freq,
    const float* __restrict__ sig_pow,
    const float* __restrict__ sig_loss,
    const float* __restrict__ lcoef,
    const float* __restrict__ overlap,
    const float* __restrict__ raman,
    const int*   __restrict__ steps_p,
    const float* __restrict__ length_p,
    const float* __restrict__ maxf_p,
    int Lr,
    float* __restrict__ out)
{
    __shared__ __align__(16) float Qt[2 * QSZ];
    __shared__ __align__(16) float ovS[16];
    __shared__ float frq[F];

    const int b = blockIdx.x;
    const int t = threadIdx.x;
    const int g = t >> 2;          // group 0..55 -> rows 2g, 2g+1
    const int q = t & 3;           // j-quarter
    const int r0 = 2 * g, r1 = 2 * g + 1;
    const int myrow = r0 + (q & 1);
    const int rowc  = min(myrow, F - 1);
    const int r0c = min(r0, F - 1), r1c = min(r1, F - 1);
    const bool active = (myrow < F);
    const int mp = q & 2;          // owned mode pair base (0 or 2)
    const float* xb = x + b * XW;

    const int   steps  = *steps_p;
    const float length = *length_p;
    const float maxf   = *maxf_p;
    const float hstep = length / (float)(steps - 1);
    const float h2 = 0.5f * hstep;
    const float h6 = hstep * (1.0f / 6.0f);

    if (t < 16) ovS[t] = overlap[t];
    for (int u = t; u < F; u += NT)
        frq[u] = (u < PNP) ? (C0F / xb[u]) : sig_freq[u - PNP];
    __syncthreads();

    // ---- gains: 2 rows x this quarter's 26 j's, packed adjacent-j pairs ----
    ull gpa[13], gpb[13];
    {
        const float scale = (float)(Lr - 1) / maxf;
        const float fa = frq[r0c], fb = frq[r1c];
        #pragma unroll 4
        for (int p = 0; p < 13; ++p) {
            const int j = 26 * q + 2 * p;
            const float fj0 = frq[j], fj1 = frq[j + 1];
            gpa[p] = pk2(gain_of(fa, fj0, raman, scale, Lr),
                         gain_of(fa, fj1, raman, scale, Lr));
            gpb[p] = pk2(gain_of(fb, fj0, raman, scale, Lr),
                         gain_of(fb, fj1, raman, scale, Lr));
        }
    }

    // ---- state for my (row, mode-pair): loss + power ----
    float lsA, lsB, P0, P1, P2, P3;
    if (rowc < PNP) {
        const float wn = xb[rowc] * 1e9f;
        const float lv = (lcoef[2] + lcoef[1] * wn + lcoef[0] * wn * wn) * ALPHA;
        lsA = lsB = lv;
        P0 = xb[PNP + 4 * rowc + 0]; P1 = xb[PNP + 4 * rowc + 1];
        P2 = xb[PNP + 4 * rowc + 2]; P3 = xb[PNP + 4 * rowc + 3];
    } else {
        const int u = 4 * rowc - PNP * MOD;
        lsA = sig_loss[u + mp]; lsB = sig_loss[u + mp + 1];
        P0 = sig_pow[u + 0]; P1 = sig_pow[u + 1];
        P2 = sig_pow[u + 2]; P3 = sig_pow[u + 3];
    }
    float pkA = mp ? P2 : P0, pkB = mp ? P3 : P1;
    float pcA = pkA, pcB = pkB, acA = 0.f, acB = 0.f;
    float fq0 = P0, fq1 = P1, fq2 = P2, fq3 = P3;

    // Q-write addresses for (myrow, modes mp, mp+1)
    const int qr = rowc / 26;
    const int jl = rowc - qr * 26;
    const int wA0 = ((mp * 7 + (jl >> 2)) * 4 + qr) * 4 + (jl & 3);
    const int wA1 = wA0 + 112;   // next mode row (7*4*4 floats)

    // ---- prologue: Q(P0) into buffer 0 ----
    {
        const ull pp01 = pk2(P0, P1), pp23 = pk2(P2, P3);
        const ulonglong2 ova = ((const ulonglong2*)ovS)[mp];
        const ulonglong2 ovb = ((const ulonglong2*)ovS)[mp + 1];
        ull t0 = 0, t1 = 0;
        fma2(t0, ova.x, pp01); fma2(t0, ova.y, pp23);
        fma2(t1, ovb.x, pp01); fma2(t1, ovb.y, pp23);
        if (active) { Qt[wA0] = up2sum(t0); Qt[wA1] = up2sum(t1); }
    }
    __syncthreads();

    const int kr = q & 1;   // which row this lane keeps in reduction

// one matvec half-pass over modes mb, mb+1 -> 4 partials (2 rows x 2 modes)
#define HALFPASS(Qc, mb, o00, o01, o10, o11)                                   \
    {                                                                          \
        ull aA0 = 0, aA1 = 0, aB0 = 0, aB1 = 0;                                \
        _Pragma("unroll")                                                      \
        for (int u = 0; u < 6; ++u) {                                          \
            const ulonglong2 v0 = *(const ulonglong2*)((Qc) + ((mb)*7+u)*16);  \
            const ulonglong2 v1 = *(const ulonglong2*)((Qc) + ((mb)*7+u+7)*16);\
            fma2(aA0, gpa[2*u], v0.x); fma2(aA0, gpa[2*u+1], v0.y);            \
            fma2(aA1, gpa[2*u], v1.x); fma2(aA1, gpa[2*u+1], v1.y);            \
            fma2(aB0, gpb[2*u], v0.x); fma2(aB0, gpb[2*u+1], v0.y);            \
            fma2(aB1, gpb[2*u], v1.x); fma2(aB1, gpb[2*u+1], v1.y);            \
        }                                                                      \
        {                                                                      \
            const ull w0 = *(const ull*)((Qc) + ((mb)*7+6)*16);                \
            const ull w1 = *(const ull*)((Qc) + ((mb)*7+13)*16);               \
            fma2(aA0, gpa[12], w0); fma2(aA1, gpa[12], w1);                    \
            fma2(aB0, gpb[12], w0); fma2(aB1, gpb[12], w1);                    \
        }                                                                      \
        o00 = up2sum(aA0); o01 = up2sum(aA1);                                  \
        o10 = up2sum(aB0); o11 = up2sum(aB1);                                  \
    }

#define STAGE(S4, RD, WR)                                                      \
    {                                                                          \
        const float* Qc = Qt + (RD) * QSZ + q * 4;                             \
        float p00, p01, p10, p11, p02, p03, p12, p13;                          \
        HALFPASS(Qc, 0, p00, p01, p10, p11)                                    \
        HALFPASS(Qc, 2, p02, p03, p12, p13)                                    \
        /* xor1: keep my row's 4 mode-partials */                              \
        float pm0, pm1, pm2, pm3;                                              \
        {                                                                      \
            const float s0 = kr ? p00 : p10, s1 = kr ? p01 : p11;              \
            const float s2 = kr ? p02 : p12, s3 = kr ? p03 : p13;              \
            pm0 = (kr ? p10 : p00) + __shfl_xor_sync(0xffffffffu, s0, 1);      \
            pm1 = (kr ? p11 : p01) + __shfl_xor_sync(0xffffffffu, s1, 1);      \
            pm2 = (kr ? p12 : p02) + __shfl_xor_sync(0xffffffffu, s2, 1);      \
            pm3 = (kr ? p13 : p03) + __shfl_xor_sync(0xffffffffu, s3, 1);      \
        }                                                                      \
        /* xor2: keep my mode pair, full-j sums */                             \
        float AmA, AmB;                                                        \
        {                                                                      \
            const float s0 = mp ? pm0 : pm2, s1 = mp ? pm1 : pm3;              \
            AmA = (mp ? pm2 : pm0) + __shfl_xor_sync(0xffffffffu, s0, 2);      \
            AmB = (mp ? pm3 : pm1) + __shfl_xor_sync(0xffffffffu, s1, 2);      \
        }                                                                      \
        const float kA = (AmA - lsA) * pkA;                                    \
        const float kB = (AmB - lsB) * pkB;                                    \
        if ((S4) == 0)      { acA = kA; acB = kB; }                            \
        else if ((S4) < 3)  { acA = fmaf(2.f, kA, acA);                        \
                              acB = fmaf(2.f, kB, acB); }                      \
        else                { acA += kA; acB += kB; }                          \
        if ((S4) < 3) {                                                        \
            const float cs = ((S4) == 2) ? hstep : h2;                         \
            pkA = fmaf(cs, kA, pcA);                                           \
            pkB = fmaf(cs, kB, pcB);                                           \
        } else {                                                               \
            pkA = fmaf(h6, acA, pcA);                                          \
            pkB = fmaf(h6, acB, pcB);                                          \
            pcA = pkA; pcB = pkB;                                              \
        }                                                                      \
        /* rebuild full pk quad with mode-pair partner (xor 2, same row) */    \
        {                                                                      \
            const float o0 = __shfl_xor_sync(0xffffffffu, pkA, 2);             \
            const float o1 = __shfl_xor_sync(0xffffffffu, pkB, 2);             \
            fq0 = mp ? o0 : pkA; fq1 = mp ? o1 : pkB;                          \
            fq2 = mp ? pkA : o0; fq3 = mp ? pkB : o1;                          \
            const ull pp01 = pk2(fq0, fq1), pp23 = pk2(fq2, fq3);              \
            const ulonglong2 ova = ((const ulonglong2*)ovS)[mp];               \
            const ulonglong2 ovb = ((const ulonglong2*)ovS)[mp + 1];           \
            ull t0 = 0, t1 = 0;                                                \
            fma2(t0, ova.x, pp01); fma2(t0, ova.y, pp23);                      \
            fma2(t1, ovb.x, pp01); fma2(t1, ovb.y, pp23);                      \
            float* Qn = Qt + (WR) * QSZ;                                       \
            if (active) { Qn[wA0] = up2sum(t0); Qn[wA1] = up2sum(t1); }        \
        }                                                                      \
        __syncthreads();                                                       \
    }

    const int nsteps = steps - 1;
    for (int st = 0; st < nsteps; ++st) {
        STAGE(0, 0, 1)
        STAGE(1, 1, 0)
        STAGE(2, 0, 1)
        STAGE(3, 1, 0)
    }
#undef STAGE
#undef HALFPASS

    if (active && myrow >= PNP && q < 2)
        *(float4*)(out + b * (NCH * MOD) + (myrow - PNP) * 4) =
            make_float4(fq0, fq1, fq2, fq3);
}

extern "C" void kernel_launch(void* const* d_in, const int* in_sizes, int n_in,
                              void* d_out, int out_size) {
    const float* x        = (const float*)d_in[0];
    const float* sig_freq = (const float*)d_in[1];
    const float* sig_pow  = (const float*)d_in[2];
    const float* sig_loss = (const float*)d_in[3];
    const float* lcoef    = (const float*)d_in[4];
    const float* overlap  = (const float*)d_in[5];
    const float* raman    = (const float*)d_in[6];
    const int*   steps_p  = (const int*)d_in[10];
    const float* length_p = (const float*)d_in[11];
    const float* maxf_p   = (const float*)d_in[12];

    const int B  = in_sizes[0] / XW;
    const int Lr = in_sizes[6];

    raman_kernel<<<B, NT>>>(x, sig_freq, sig_pow, sig_loss, lcoef, overlap,
                            raman, steps_p, length_p, maxf_p, Lr,
                            (float*)d_out);
}

// round 14
// speedup vs baseline: 1.8185x; 1.8185x over previous
#include <cuda_runtime.h>
#include <cuda_fp16.h>
#include <cstdint>

namespace {
constexpr int PNP = 4;
constexpr int MOD = 4;
constexpr int NCH = 100;
constexpr int F   = NCH + PNP;        // 104
constexpr int XW  = PNP * (1 + MOD);  // 20
constexpr int NT  = 128;              // 4 warps; thread t = row t for ODE state
constexpr int KT  = 7;                // k-tiles (K = 112 padded)
constexpr int MTL = 7;                // m-tiles (M = 112 padded)
constexpr float C0F   = 299792458.0f;
constexpr float ALPHA = 2.3025850929940457e-4f;
constexpr float GSC = 8796093022208.0f;        // 2^43  gain up-scale
constexpr float QSC = 9.5367431640625e-7f;     // 2^-20 Q down-scale
constexpr float DSC = 1.1920928955078125e-7f;  // 2^-23 D un-scale
constexpr int LUTMAX = 1024;
}

__device__ __forceinline__ void mma16816(float* c, const uint32_t* a,
                                         uint32_t b0, uint32_t b1) {
    asm volatile(
        "mma.sync.aligned.m16n8k16.row.col.f32.f16.f16.f32 "
        "{%0,%1,%2,%3}, {%4,%5,%6,%7}, {%8,%9}, {%0,%1,%2,%3};"
        : "+f"(c[0]), "+f"(c[1]), "+f"(c[2]), "+f"(c[3])
        : "r"(a[0]), "r"(a[1]), "r"(a[2]), "r"(a[3]), "r"(b0), "r"(b1));
}

__device__ __forceinline__ uint32_t pack_hl(float x, float y, uint32_t& lo) {
    const __half hx = __float2half_rn(x), hy = __float2half_rn(y);
    const __half lx = __float2half_rn(x - __half2float(hx));
    const __half ly = __float2half_rn(y - __half2float(hy));
    const __half2 h = __halves2half2(hx, hy);
    const __half2 l = __halves2half2(lx, ly);
    lo = *(const uint32_t*)&l;
    return *(const uint32_t*)&h;
}

__device__ __forceinline__ float gval(int r, int c, const float* frq,
                                      const float* lutp, float scale, int Lr) {
    if (r >= F || c >= F) return 0.0f;
    const float fi = frq[r], fj = frq[c];
    const float fd = fj - fi;
    const float pos = fabsf(fd) * scale;
    int i0 = (int)floorf(pos);
    i0 = min(max(i0, 0), Lr - 2);
    const float w = pos - (float)i0;
    float g = lutp[i0] * (1.0f - w) + lutp[i0 + 1] * w;
    if (fd < 0.0f) g = -g;
    return g * fmaxf(1.0f, fi / fj) * GSC;
}

__global__ __launch_bounds__(NT, 4) void raman_kernel(
    const float* __restrict__ x,
    const float* __restrict__ sig_freq,
    const float* __restrict__ sig_pow,
    const float* __restrict__ sig_loss,
    const float* __restrict__ lcoef,
    const float* __restrict__ overlap,
    const float* __restrict__ raman,
    const int*   __restrict__ steps_p,
    const float* __restrict__ length_p,
    const float* __restrict__ maxf_p,
    int Lr,
    float* __restrict__ out)
{
    __shared__ uint4    Asm[MTL * KT][32];     // G-lo fragments, 25088 B
    __shared__ uint32_t Qb[2][KT * 16 * 2];    // B frags hi/lo, 1792 B
    __shared__ float    Ds[112][4];            // D tile, 1792 B
    __shared__ float    frq[F];
    __shared__ float    ovS[16];
    __shared__ float    lut[LUTMAX];

    const int b = blockIdx.x;
    const int t = threadIdx.x;
    const int wid = t >> 5;
    const int lane = t & 31;
    const int g_ = lane >> 2;     // group (row-in-tile / N col)
    const int tig = lane & 3;     // thread-in-group
    const bool rowok = (t < F);
    const int rowc = min(t, F - 1);
    const float* xb = x + b * XW;

    const int   steps  = *steps_p;
    const float length = *length_p;
    const float maxf   = *maxf_p;
    const float hstep = length / (float)(steps - 1);
    const float h2 = 0.5f * hstep;
    const float h6 = hstep * (1.0f / 6.0f);

    // ---- init shared ----
    for (int u = t; u < 2 * KT * 16 * 2; u += NT) ((uint32_t*)Qb)[u] = 0u;
    if (t < 16) ovS[t] = overlap[t] * QSC;
    for (int u = t; u < F; u += NT)
        frq[u] = (u < PNP) ? (C0F / xb[u]) : sig_freq[u - PNP];
    for (int u = t; u < Lr && u < LUTMAX; u += NT) lut[u] = raman[u];
    __syncthreads();

    const float* lutp = (Lr <= LUTMAX) ? lut : raman;
    const float scale = (float)(Lr - 1) / maxf;

    // ---- G fragments: hi in regs, lo in smem. warp w owns m-tiles w, w+4 ----
    uint32_t Ah[2][KT][4];
    #pragma unroll
    for (int s = 0; s < 2; ++s) {
        const int mt = wid + 4 * s;
        #pragma unroll
        for (int kt = 0; kt < KT; ++kt) {
            uint32_t al[4] = {0u, 0u, 0u, 0u};
            uint32_t ah[4] = {0u, 0u, 0u, 0u};
            if (mt < MTL) {
                const int r0 = mt * 16 + g_, r1 = r0 + 8;
                const int cb = kt * 16 + 2 * tig;
                ah[0] = pack_hl(gval(r0, cb,     frq, lutp, scale, Lr),
                                gval(r0, cb + 1, frq, lutp, scale, Lr), al[0]);
                ah[1] = pack_hl(gval(r1, cb,     frq, lutp, scale, Lr),
                                gval(r1, cb + 1, frq, lutp, scale, Lr), al[1]);
                ah[2] = pack_hl(gval(r0, cb + 8, frq, lutp, scale, Lr),
                                gval(r0, cb + 9, frq, lutp, scale, Lr), al[2]);
                ah[3] = pack_hl(gval(r1, cb + 8, frq, lutp, scale, Lr),
                                gval(r1, cb + 9, frq, lutp, scale, Lr), al[3]);
                Asm[mt * KT + kt][lane] = make_uint4(al[0], al[1], al[2], al[3]);
            }
            Ah[s][kt][0] = ah[0]; Ah[s][kt][1] = ah[1];
            Ah[s][kt][2] = ah[2]; Ah[s][kt][3] = ah[3];
        }
    }

    // ---- per-row loss + initial power ----
    float ls0, ls1, ls2, ls3, pk0, pk1, pk2, pk3;
    if (rowc < PNP) {
        const float wn = xb[rowc] * 1e9f;
        const float lv = (lcoef[2] + lcoef[1] * wn + lcoef[0] * wn * wn) * ALPHA;
        ls0 = ls1 = ls2 = ls3 = lv;
        pk0 = xb[PNP + 4 * rowc + 0]; pk1 = xb[PNP + 4 * rowc + 1];
        pk2 = xb[PNP + 4 * rowc + 2]; pk3 = xb[PNP + 4 * rowc + 3];
    } else {
        const int u = 4 * rowc - PNP * MOD;
        ls0 = sig_loss[u + 0]; ls1 = sig_loss[u + 1];
        ls2 = sig_loss[u + 2]; ls3 = sig_loss[u + 3];
        pk0 = sig_pow[u + 0]; pk1 = sig_pow[u + 1];
        pk2 = sig_pow[u + 2]; pk3 = sig_pow[u + 3];
    }
    float pc0 = pk0, pc1 = pk1, pc2 = pk2, pc3 = pk3;
    float ac0 = 0.f, ac1 = 0.f, ac2 = 0.f, ac3 = 0.f;

    // B-fragment byte offsets for this row (j = t): 4 modes, hi buffer
    int qoff[4];
    {
        const int r_ = t & 15, kt_ = t >> 4;
        const int lq = (r_ & 7) >> 1, rg = r_ >> 3, hb = r_ & 1;
        #pragma unroll
        for (int m = 0; m < 4; ++m)
            qoff[m] = (((kt_ * 16 + (m * 4 + lq)) * 2 + rg) << 2) + hb * 2;
    }
    char* Qh = (char*)&Qb[0][0];
    char* Ql = (char*)&Qb[1][0];

#define PUT_Q()                                                                \
    if (rowok) {                                                               \
        const float4 o0 = *(const float4*)(ovS + 0);                           \
        const float4 o1 = *(const float4*)(ovS + 4);                           \
        const float4 o2 = *(const float4*)(ovS + 8);                           \
        const float4 o3 = *(const float4*)(ovS + 12);                          \
        const float q0 = o0.x*pk0 + o0.y*pk1 + o0.z*pk2 + o0.w*pk3;            \
        const float q1 = o1.x*pk0 + o1.y*pk1 + o1.z*pk2 + o1.w*pk3;            \
        const float q2 = o2.x*pk0 + o2.y*pk1 + o2.z*pk2 + o2.w*pk3;            \
        const float q3 = o3.x*pk0 + o3.y*pk1 + o3.z*pk2 + o3.w*pk3;            \
        const __half h0 = __float2half_rn(q0), h1 = __float2half_rn(q1);       \
        const __half h2_ = __float2half_rn(q2), h3 = __float2half_rn(q3);      \
        *(__half*)(Qh + qoff[0]) = h0; *(__half*)(Qh + qoff[1]) = h1;          \
        *(__half*)(Qh + qoff[2]) = h2_; *(__half*)(Qh + qoff[3]) = h3;         \
        *(__half*)(Ql + qoff[0]) = __float2half_rn(q0 - __half2float(h0));     \
        *(__half*)(Ql + qoff[1]) = __float2half_rn(q1 - __half2float(h1));     \
        *(__half*)(Ql + qoff[2]) = __float2half_rn(q2 - __half2float(h2_));    \
        *(__half*)(Ql + qoff[3]) = __float2half_rn(q3 - __half2float(h3));     \
    }

    PUT_Q();
    __syncthreads();

    const int nst = 4 * (steps - 1);
    for (int it = 0; it < nst; ++it) {
        const int s4 = it & 3;

        // ---- tensor-core matvec ----
        float C1[2][4] = {{0.f,0.f,0.f,0.f},{0.f,0.f,0.f,0.f}};
        float C2[2][4] = {{0.f,0.f,0.f,0.f},{0.f,0.f,0.f,0.f}};
        #pragma unroll
        for (int kt = 0; kt < KT; ++kt) {
            uint32_t bh0 = 0u, bh1 = 0u, bl0 = 0u, bl1 = 0u;
            if (lane < 16) {
                const uint2 vh = ((const uint2*)&Qb[0][0])[kt * 16 + lane];
                const uint2 vl = ((const uint2*)&Qb[1][0])[kt * 16 + lane];
                bh0 = vh.x; bh1 = vh.y; bl0 = vl.x; bl1 = vl.y;
            }
            #pragma unroll
            for (int s = 0; s < 2; ++s) {
                const int mt = wid + 4 * s;
                if (mt < MTL) {
                    const uint4 alv = Asm[mt * KT + kt][lane];
                    uint32_t al[4] = {alv.x, alv.y, alv.z, alv.w};
                    mma16816(C1[s], Ah[s][kt], bh0, bh1);
                    mma16816(C2[s], Ah[s][kt], bl0, bl1);
                    mma16816(C2[s], al, bh0, bh1);
                }
            }
        }
        // ---- D -> smem (cols 0..3 live in lanes tig<2) ----
        #pragma unroll
        for (int s = 0; s < 2; ++s) {
            const int mt = wid + 4 * s;
            if (mt < MTL && tig < 2) {
                const int row = mt * 16 + g_;
                *(float2*)&Ds[row][2 * tig] =
                    make_float2(C1[s][0] + C2[s][0], C1[s][1] + C2[s][1]);
                *(float2*)&Ds[row + 8][2 * tig] =
                    make_float2(C1[s][2] + C2[s][2], C1[s][3] + C2[s][3]);
            }
        }
        __syncthreads();

        // ---- RK update + next Q ----
        if (rowok) {
            const float4 dv = *(const float4*)Ds[t];
            const float A0 = dv.x * DSC, A1 = dv.y * DSC;
            const float A2 = dv.z * DSC, A3 = dv.w * DSC;
            const float k0 = (A0 - ls0) * pk0;
            const float k1 = (A1 - ls1) * pk1;
            const float k2 = (A2 - ls2) * pk2;
            const float k3 = (A3 - ls3) * pk3;
            if (s4 == 0)      { ac0 = k0; ac1 = k1; ac2 = k2; ac3 = k3; }
            else if (s4 < 3)  { ac0 = fmaf(2.f, k0, ac0); ac1 = fmaf(2.f, k1, ac1);
                                ac2 = fmaf(2.f, k2, ac2); ac3 = fmaf(2.f, k3, ac3); }
            else              { ac0 += k0; ac1 += k1; ac2 += k2; ac3 += k3; }
            if (s4 < 3) {
                const float cs = (s4 == 2) ? hstep : h2;
                pk0 = fmaf(cs, k0, pc0); pk1 = fmaf(cs, k1, pc1);
                pk2 = fmaf(cs, k2, pc2); pk3 = fmaf(cs, k3, pc3);
            } else {
                pk0 = fmaf(h6, ac0, pc0); pk1 = fmaf(h6, ac1, pc1);
                pk2 = fmaf(h6, ac2, pc2); pk3 = fmaf(h6, ac3, pc3);
                pc0 = pk0; pc1 = pk1; pc2 = pk2; pc3 = pk3;
            }
        }
        PUT_Q();
        __syncthreads();
    }
#undef PUT_Q

    if (rowok && t >= PNP)
        *(float4*)(out + b * (NCH * MOD) + (t - PNP) * 4) =
            make_float4(pk0, pk1, pk2, pk3);
}

extern "C" void kernel_launch(void* const* d_in, const int* in_sizes, int n_in,
                              void* d_out, int out_size) {
    const float* x        = (const float*)d_in[0];
    const float* sig_freq = (const float*)d_in[1];
    const float* sig_pow  = (const float*)d_in[2];
    const float* sig_loss = (const float*)d_in[3];
    const float* lcoef    = (const float*)d_in[4];
    const float* overlap  = (const float*)d_in[5];
    const float* raman    = (const float*)d_in[6];
    const int*   steps_p  = (const int*)d_in[10];
    const float* length_p = (const float*)d_in[11];
    const float* maxf_p   = (const float*)d_in[12];

    const int B  = in_sizes[0] / XW;
    const int Lr = in_sizes[6];

    raman_kernel<<<B, NT>>>(x, sig_freq, sig_pow, sig_loss, lcoef, overlap,
                            raman, steps_p, length_p, maxf_p, Lr,
                            (float*)d_out);
}

// round 15
// speedup vs baseline: 1.9445x; 1.0693x over previous
#include <cuda_runtime.h>
#include <cuda_fp16.h>
#include <cuda_fp8.h>
#include <cstdint>

namespace {
constexpr int PNP = 4;
constexpr int MOD = 4;
constexpr int NCH = 100;
constexpr int F   = NCH + PNP;        // 104
constexpr int XW  = PNP * (1 + MOD);  // 20
constexpr int NT  = 128;              // 4 warps; thread t = row t
constexpr int KT  = 7;                // k-tiles (K = 112)
constexpr int MTL = 7;                // m-tiles (M = 112)
constexpr float C0F   = 299792458.0f;
constexpr float ALPHA = 2.3025850929940457e-4f;
constexpr float GSC = 8796093022208.0f;        // 2^43  gain up-scale
constexpr float QSC = 9.5367431640625e-7f;     // 2^-20 Q down-scale
constexpr float DSC = 1.1920928955078125e-7f;  // 2^-23 D un-scale
constexpr float ASC  = 2048.0f;                // 2^11  G-lo up-scale (fp8)
constexpr float ASCI = 4.8828125e-4f;          // 2^-11
constexpr int LUTMAX = 1024;
}

__device__ __forceinline__ void mma16816(float* c, const uint32_t* a,
                                         uint32_t b0, uint32_t b1) {
    asm volatile(
        "mma.sync.aligned.m16n8k16.row.col.f32.f16.f16.f32 "
        "{%0,%1,%2,%3}, {%4,%5,%6,%7}, {%8,%9}, {%0,%1,%2,%3};"
        : "+f"(c[0]), "+f"(c[1]), "+f"(c[2]), "+f"(c[3])
        : "r"(a[0]), "r"(a[1]), "r"(a[2]), "r"(a[3]), "r"(b0), "r"(b1));
}

__device__ __forceinline__ float gval(int r, int c, const float* frq,
                                      const float* lutp, float scale, int Lr) {
    if (r >= F || c >= F) return 0.0f;
    const float fi = frq[r], fj = frq[c];
    const float fd = fj - fi;
    const float pos = fabsf(fd) * scale;
    int i0 = (int)floorf(pos);
    i0 = min(max(i0, 0), Lr - 2);
    const float w = pos - (float)i0;
    float g = lutp[i0] * (1.0f - w) + lutp[i0 + 1] * w;
    if (fd < 0.0f) g = -g;
    return g * fmaxf(1.0f, fi / fj) * GSC;
}

// pack two floats to fp16x2 (x -> low) and return fp8(e4m3) residual pair
__device__ __forceinline__ uint32_t pack_h8(float x, float y, uint16_t& lo8) {
    const __half hx = __float2half_rn(x), hy = __float2half_rn(y);
    const float rx = (x - __half2float(hx)) * ASC;
    const float ry = (y - __half2float(hy)) * ASC;
    __nv_fp8x2_e4m3 p(make_float2(rx, ry));
    lo8 = (uint16_t)p.__x;
    const __half2 h = __halves2half2(hx, hy);
    return *(const uint32_t*)&h;
}

__device__ __forceinline__ uint32_t fp8pair_to_h2(uint16_t v) {
    __nv_fp8x2_e4m3 p; p.__x = (__nv_fp8x2_storage_t)v;
    const __half2 h = (__half2)p;
    return *(const uint32_t*)&h;
}

__global__ __launch_bounds__(NT, 4) void raman_kernel(
    const float* __restrict__ x,
    const float* __restrict__ sig_freq,
    const float* __restrict__ sig_pow,
    const float* __restrict__ sig_loss,
    const float* __restrict__ lcoef,
    const float* __restrict__ overlap,
    const float* __restrict__ raman,
    const int*   __restrict__ steps_p,
    const float* __restrict__ length_p,
    const float* __restrict__ maxf_p,
    int Lr,
    float* __restrict__ out)
{
    __shared__ uint2    Asm8[MTL * KT][32];   // G-lo fp8 frags, 12544 B
    __shared__ uint2    Qb2[KT * 32];         // B frags (Qh cols0-3, Ql cols4-7)
    __shared__ float    Dsum[112][4];         // GhQh + 2^-11 GlQh
    __shared__ float    Dsb[112][4];          // GhQl
    __shared__ float    frq[F];
    __shared__ float    ovS[16];
    __shared__ float    lut[LUTMAX];

    const int b = blockIdx.x;
    const int t = threadIdx.x;
    const int wid = t >> 5;
    const int lane = t & 31;
    const int g_ = lane >> 2;
    const int tig = lane & 3;
    const bool rowok = (t < F);
    const int rowc = min(t, F - 1);
    const float* xb = x + b * XW;

    const int   steps  = *steps_p;
    const float length = *length_p;
    const float maxf   = *maxf_p;
    const float hstep = length / (float)(steps - 1);
    const float h2 = 0.5f * hstep;
    const float h6 = hstep * (1.0f / 6.0f);

    for (int u = t; u < KT * 32 * 2; u += NT) ((uint32_t*)Qb2)[u] = 0u;
    if (t < 16) ovS[t] = overlap[t] * QSC;
    for (int u = t; u < F; u += NT)
        frq[u] = (u < PNP) ? (C0F / xb[u]) : sig_freq[u - PNP];
    for (int u = t; u < Lr && u < LUTMAX; u += NT) lut[u] = raman[u];
    __syncthreads();

    const float* lutp = (Lr <= LUTMAX) ? lut : raman;
    const float scale = (float)(Lr - 1) / maxf;

    // ---- G fragments: hi fp16 in regs, lo fp8 in smem ----
    uint32_t Ah[2][KT][4];
    #pragma unroll
    for (int s = 0; s < 2; ++s) {
        const int mt = wid + 4 * s;
        #pragma unroll
        for (int kt = 0; kt < KT; ++kt) {
            uint32_t ah[4] = {0u, 0u, 0u, 0u};
            uint16_t l8[4] = {0, 0, 0, 0};
            if (mt < MTL) {
                const int r0 = mt * 16 + g_, r1 = r0 + 8;
                const int cb = kt * 16 + 2 * tig;
                ah[0] = pack_h8(gval(r0, cb,     frq, lutp, scale, Lr),
                                gval(r0, cb + 1, frq, lutp, scale, Lr), l8[0]);
                ah[1] = pack_h8(gval(r1, cb,     frq, lutp, scale, Lr),
                                gval(r1, cb + 1, frq, lutp, scale, Lr), l8[1]);
                ah[2] = pack_h8(gval(r0, cb + 8, frq, lutp, scale, Lr),
                                gval(r0, cb + 9, frq, lutp, scale, Lr), l8[2]);
                ah[3] = pack_h8(gval(r1, cb + 8, frq, lutp, scale, Lr),
                                gval(r1, cb + 9, frq, lutp, scale, Lr), l8[3]);
                Asm8[mt * KT + kt][lane] =
                    make_uint2((uint32_t)l8[0] | ((uint32_t)l8[1] << 16),
                               (uint32_t)l8[2] | ((uint32_t)l8[3] << 16));
            }
            Ah[s][kt][0] = ah[0]; Ah[s][kt][1] = ah[1];
            Ah[s][kt][2] = ah[2]; Ah[s][kt][3] = ah[3];
        }
    }

    // ---- per-row loss + initial power ----
    float ls0, ls1, ls2, ls3, pk0, pk1, pk2, pk3;
    if (rowc < PNP) {
        const float wn = xb[rowc] * 1e9f;
        const float lv = (lcoef[2] + lcoef[1] * wn + lcoef[0] * wn * wn) * ALPHA;
        ls0 = ls1 = ls2 = ls3 = lv;
        pk0 = xb[PNP + 4 * rowc + 0]; pk1 = xb[PNP + 4 * rowc + 1];
        pk2 = xb[PNP + 4 * rowc + 2]; pk3 = xb[PNP + 4 * rowc + 3];
    } else {
        const int u = 4 * rowc - PNP * MOD;
        ls0 = sig_loss[u + 0]; ls1 = sig_loss[u + 1];
        ls2 = sig_loss[u + 2]; ls3 = sig_loss[u + 3];
        pk0 = sig_pow[u + 0]; pk1 = sig_pow[u + 1];
        pk2 = sig_pow[u + 2]; pk3 = sig_pow[u + 3];
    }
    float pc0 = pk0, pc1 = pk1, pc2 = pk2, pc3 = pk3;
    float ac0 = 0.f, ac1 = 0.f, ac2 = 0.f, ac3 = 0.f;

    // B byte offsets: col c in {m} (hi) and {4+m} (lo), row k = t%16, tile t/16
    int qofh[4], qofl[4];
    {
        const int r_ = t & 15, kt_ = t >> 4;
        const int lq = (r_ & 7) >> 1, rg = r_ >> 3, hb = r_ & 1;
        #pragma unroll
        for (int m = 0; m < 4; ++m) {
            qofh[m] = (kt_ * 32 + m * 4 + lq) * 8 + rg * 4 + hb * 2;
            qofl[m] = (kt_ * 32 + (4 + m) * 4 + lq) * 8 + rg * 4 + hb * 2;
        }
    }
    char* Qc = (char*)Qb2;

#define PUT_Q()                                                                \
    if (rowok) {                                                               \
        const float4 o0 = *(const float4*)(ovS + 0);                           \
        const float4 o1 = *(const float4*)(ovS + 4);                           \
        const float4 o2 = *(const float4*)(ovS + 8);                           \
        const float4 o3 = *(const float4*)(ovS + 12);                          \
        const float q0 = o0.x*pk0 + o0.y*pk1 + o0.z*pk2 + o0.w*pk3;            \
        const float q1 = o1.x*pk0 + o1.y*pk1 + o1.z*pk2 + o1.w*pk3;            \
        const float q2 = o2.x*pk0 + o2.y*pk1 + o2.z*pk2 + o2.w*pk3;            \
        const float q3 = o3.x*pk0 + o3.y*pk1 + o3.z*pk2 + o3.w*pk3;            \
        const __half h0 = __float2half_rn(q0), h1 = __float2half_rn(q1);       \
        const __half h2_ = __float2half_rn(q2), h3 = __float2half_rn(q3);      \
        *(__half*)(Qc + qofh[0]) = h0; *(__half*)(Qc + qofh[1]) = h1;          \
        *(__half*)(Qc + qofh[2]) = h2_; *(__half*)(Qc + qofh[3]) = h3;         \
        *(__half*)(Qc + qofl[0]) = __float2half_rn(q0 - __half2float(h0));     \
        *(__half*)(Qc + qofl[1]) = __float2half_rn(q1 - __half2float(h1));     \
        *(__half*)(Qc + qofl[2]) = __float2half_rn(q2 - __half2float(h2_));    \
        *(__half*)(Qc + qofl[3]) = __float2half_rn(q3 - __half2float(h3));     \
    }

    PUT_Q();
    __syncthreads();

    const int nst = 4 * (steps - 1);
    for (int it = 0; it < nst; ++it) {
        const int s4 = it & 3;

        // ---- tensor matvec: C1 = Gh·[Qh|Ql], C2 = Gl8·[Qh|Ql] ----
        float C1[2][4] = {{0.f,0.f,0.f,0.f},{0.f,0.f,0.f,0.f}};
        float C2[2][4] = {{0.f,0.f,0.f,0.f},{0.f,0.f,0.f,0.f}};
        #pragma unroll
        for (int kt = 0; kt < KT; ++kt) {
            const uint2 v = Qb2[kt * 32 + lane];
            #pragma unroll
            for (int s = 0; s < 2; ++s) {
                const int mt = wid + 4 * s;
                if (mt < MTL) {
                    const uint2 a8 = Asm8[mt * KT + kt][lane];
                    uint32_t al[4];
                    al[0] = fp8pair_to_h2((uint16_t)(a8.x & 0xffffu));
                    al[1] = fp8pair_to_h2((uint16_t)(a8.x >> 16));
                    al[2] = fp8pair_to_h2((uint16_t)(a8.y & 0xffffu));
                    al[3] = fp8pair_to_h2((uint16_t)(a8.y >> 16));
                    mma16816(C1[s], Ah[s][kt], v.x, v.y);
                    mma16816(C2[s], al, v.x, v.y);
                }
            }
        }
        // ---- D -> smem ----
        #pragma unroll
        for (int s = 0; s < 2; ++s) {
            const int mt = wid + 4 * s;
            if (mt < MTL) {
                const int row = mt * 16 + g_;
                if (tig < 2) {  // cols 0-3: main + fp8 correction
                    *(float2*)&Dsum[row][2 * tig] = make_float2(
                        fmaf(ASCI, C2[s][0], C1[s][0]),
                        fmaf(ASCI, C2[s][1], C1[s][1]));
                    *(float2*)&Dsum[row + 8][2 * tig] = make_float2(
                        fmaf(ASCI, C2[s][2], C1[s][2]),
                        fmaf(ASCI, C2[s][3], C1[s][3]));
                } else {        // cols 4-7: Gh·Ql correction for modes 0-3
                    *(float2*)&Dsb[row][2 * (tig - 2)] =
                        make_float2(C1[s][0], C1[s][1]);
                    *(float2*)&Dsb[row + 8][2 * (tig - 2)] =
                        make_float2(C1[s][2], C1[s][3]);
                }
            }
        }
        __syncthreads();

        // ---- RK update + next Q ----
        if (rowok) {
            const float4 d1 = *(const float4*)Dsum[t];
            const float4 d2 = *(const float4*)Dsb[t];
            const float A0 = (d1.x + d2.x) * DSC;
            const float A1 = (d1.y + d2.y) * DSC;
            const float A2 = (d1.z + d2.z) * DSC;
            const float A3 = (d1.w + d2.w) * DSC;
            const float k0 = (A0 - ls0) * pk0;
            const float k1 = (A1 - ls1) * pk1;
            const float k2 = (A2 - ls2) * pk2;
            const float k3 = (A3 - ls3) * pk3;
            if (s4 == 0)      { ac0 = k0; ac1 = k1; ac2 = k2; ac3 = k3; }
            else if (s4 < 3)  { ac0 = fmaf(2.f, k0, ac0); ac1 = fmaf(2.f, k1, ac1);
                                ac2 = fmaf(2.f, k2, ac2); ac3 = fmaf(2.f, k3, ac3); }
            else              { ac0 += k0; ac1 += k1; ac2 += k2; ac3 += k3; }
            if (s4 < 3) {
                const float cs = (s4 == 2) ? hstep : h2;
                pk0 = fmaf(cs, k0, pc0); pk1 = fmaf(cs, k1, pc1);
                pk2 = fmaf(cs, k2, pc2); pk3 = fmaf(cs, k3, pc3);
            } else {
                pk0 = fmaf(h6, ac0, pc0); pk1 = fmaf(h6, ac1, pc1);
                pk2 = fmaf(h6, ac2, pc2); pk3 = fmaf(h6, ac3, pc3);
                pc0 = pk0; pc1 = pk1; pc2 = pk2; pc3 = pk3;
            }
        }
        PUT_Q();
        __syncthreads();
    }
#undef PUT_Q

    if (rowok && t >= PNP)
        *(float4*)(out + b * (NCH * MOD) + (t - PNP) * 4) =
            make_float4(pk0, pk1, pk2, pk3);
}

extern "C" void kernel_launch(void* const* d_in, const int* in_sizes, int n_in,
                              void* d_out, int out_size) {
    const float* x        = (const float*)d_in[0];
    const float* sig_freq = (const float*)d_in[1];
    const float* sig_pow  = (const float*)d_in[2];
    const float* sig_loss = (const float*)d_in[3];
    const float* lcoef    = (const float*)d_in[4];
    const float* overlap  = (const float*)d_in[5];
    const float* raman    = (const float*)d_in[6];
    const int*   steps_p  = (const int*)d_in[10];
    const float* length_p = (const float*)d_in[11];
    const float* maxf_p   = (const float*)d_in[12];

    const int B  = in_sizes[0] / XW;
    const int Lr = in_sizes[6];

    raman_kernel<<<B, NT>>>(x, sig_freq, sig_pow, sig_loss, lcoef, overlap,
                            raman, steps_p, length_p, maxf_p, Lr,
                            (float*)d_out);
}